// round 16
// baseline (speedup 1.0000x reference)
#include <cuda_runtime.h>

// Problem constants (fixed by the benchmark shapes)
constexpr int kB  = 4;
constexpr int kV  = 512;
constexpr int kH  = 128;
constexpr int kTI = 4;               // query rows per block in kernel 2

// Scratch (allocation-free rule: __device__ globals)
__device__ float g_h [kB * kV * kH]; // h = x @ W^T + b   (1 MB)
__device__ float g_si[kB * kV];
__device__ float g_sj[kB * kV];

// ---------------------------------------------------------------------------
// Kernel 1: h = x @ W_w^T + W_b ; s_i = h . a_i ; s_j = h . a_j
// One block per (b,v) row, 128 threads (thread = output channel o).
// ---------------------------------------------------------------------------
__global__ void __launch_bounds__(128)
gat_k1(const float* __restrict__ x,
       const float* __restrict__ Ww,
       const float* __restrict__ Wb,
       const float* __restrict__ a)
{
    const int row = blockIdx.x;          // b*V + v
    const int t   = threadIdx.x;         // 0..127

    __shared__ __align__(16) float xs[kH];
    __shared__ float rs[4], rj[4];

    xs[t] = x[(size_t)row * kH + t];
    __syncthreads();

    const float4* xs4 = reinterpret_cast<const float4*>(xs);
    const float4* W4  = reinterpret_cast<const float4*>(Ww + (size_t)t * kH);

    float acc = Wb[t];
#pragma unroll
    for (int d = 0; d < kH / 4; d++) {
        float4 wv = W4[d];
        float4 xv = xs4[d];
        acc += wv.x * xv.x;
        acc += wv.y * xv.y;
        acc += wv.z * xv.z;
        acc += wv.w * xv.w;
    }
    g_h[(size_t)row * kH + t] = acc;

    // a layout: (1, NH=8, 2*HD=32). channel t -> head n = t>>4, k = t&15
    const int n = t >> 4, k = t & 15;
    float si = acc * a[n * 32 + k];
    float sj = acc * a[n * 32 + 16 + k];
#pragma unroll
    for (int o = 16; o; o >>= 1) {
        si += __shfl_xor_sync(0xffffffffu, si, o);
        sj += __shfl_xor_sync(0xffffffffu, sj, o);
    }
    if ((t & 31) == 0) { rs[t >> 5] = si; rj[t >> 5] = sj; }
    __syncthreads();
    if (t == 0) {
        g_si[row] = (rs[0] + rs[1]) + (rs[2] + rs[3]);
        g_sj[row] = (rj[0] + rj[1]) + (rj[2] + rj[3]);
    }
}

// ---------------------------------------------------------------------------
// Kernel 2: per block = (b, 4 consecutive query rows i0..i0+3)
//   A) score[r][j] = leaky_relu(s_i[r]+s_j[j]) * mean_h(edge_gate[b,i,j,:])
//   B) softmax over j (per row)
//   C) attended[r][:] = sum_j w[r][j] * h[b,j,:]   (h L2-resident, 4x reuse)
//   D) out[b,i,:] = attended @ Wo^T + Wo_b         (Wo L1-resident)
// 256 threads, 8 warps.
// ---------------------------------------------------------------------------
__global__ void __launch_bounds__(256)
gat_k2(const float* __restrict__ eg,
       const float* __restrict__ Wo,
       const float* __restrict__ Wob,
       float* __restrict__ out)
{
    const int blk  = blockIdx.x;                 // 0..511
    const int b    = blk >> 7;                   // 128 i-tiles per batch
    const int i0   = (blk & 127) * kTI;
    const int t    = threadIdx.x;
    const int lane = t & 31;
    const int w    = t >> 5;                     // warp id 0..7

    __shared__ float wS[kTI * kV];               // scores -> weights (8 KB)
    __shared__ __align__(16) float attS[2 * kTI * kH]; // partial attended (4 KB)
    __shared__ float sjS[kV];                    // s_j for this batch (2 KB)
    __shared__ float mred[kTI][2], sred[kTI][2];

    // preload s_j row and s_i for our 4 query rows
    sjS[t]       = g_sj[b * kV + t];
    sjS[t + 256] = g_sj[b * kV + t + 256];
    float sib[kTI];
#pragma unroll
    for (int r = 0; r < kTI; r++) sib[r] = g_si[b * kV + i0 + r];
    __syncthreads();

    // ---------- Phase A: stream edge_gate, compute masked leaky scores ------
    {
        const int   r     = w >> 1;                     // warps 2r,2r+1 share row r
        const int   jbase = (w & 1) * 256;
        const float sirow = sib[r];
        const float* egrow = eg + ((size_t)(b * kV + i0 + r)) * kV * kH;

        for (int q = 0; q < 256; q += 4) {
            const int j = jbase + q;
            const float4* p = reinterpret_cast<const float4*>(egrow + (size_t)j * kH) + lane;
            // 4 j-rows in flight per lane: 4 independent LDG.128 (MLP)
            float4 v0 = p[0], v1 = p[32], v2 = p[64], v3 = p[96];
            float p0 = (v0.x + v0.y) + (v0.z + v0.w);
            float p1 = (v1.x + v1.y) + (v1.z + v1.w);
            float p2 = (v2.x + v2.y) + (v2.z + v2.w);
            float p3 = (v3.x + v3.y) + (v3.z + v3.w);
#pragma unroll
            for (int o = 16; o; o >>= 1) {
                p0 += __shfl_xor_sync(0xffffffffu, p0, o);
                p1 += __shfl_xor_sync(0xffffffffu, p1, o);
                p2 += __shfl_xor_sync(0xffffffffu, p2, o);
                p3 += __shfl_xor_sync(0xffffffffu, p3, o);
            }
            if (lane == 0) {
                float s0 = sirow + sjS[j + 0]; s0 = s0 > 0.f ? s0 : 0.2f * s0;
                float s1 = sirow + sjS[j + 1]; s1 = s1 > 0.f ? s1 : 0.2f * s1;
                float s2 = sirow + sjS[j + 2]; s2 = s2 > 0.f ? s2 : 0.2f * s2;
                float s3 = sirow + sjS[j + 3]; s3 = s3 > 0.f ? s3 : 0.2f * s3;
                wS[r * kV + j + 0] = s0 * (p0 * (1.f / 128.f));
                wS[r * kV + j + 1] = s1 * (p1 * (1.f / 128.f));
                wS[r * kV + j + 2] = s2 * (p2 * (1.f / 128.f));
                wS[r * kV + j + 3] = s3 * (p3 * (1.f / 128.f));
            }
        }
    }
    __syncthreads();

    // ---------- Phase B: softmax over j, per row (64 threads / row) ---------
    {
        const int rr = t >> 6;           // row 0..3
        const int c  = t & 63;           // 64 threads per row, 8 elems each
        float* rowp = wS + rr * kV + c * 8;

        float m = rowp[0];
#pragma unroll
        for (int q = 1; q < 8; q++) m = fmaxf(m, rowp[q]);
#pragma unroll
        for (int o = 16; o; o >>= 1) m = fmaxf(m, __shfl_xor_sync(0xffffffffu, m, o));
        if (lane == 0) mred[rr][(t >> 5) & 1] = m;
        __syncthreads();
        const float M = fmaxf(mred[rr][0], mred[rr][1]);

        float e[8];
        float s = 0.f;
#pragma unroll
        for (int q = 0; q < 8; q++) { e[q] = __expf(rowp[q] - M); s += e[q]; }
#pragma unroll
        for (int o = 16; o; o >>= 1) s += __shfl_xor_sync(0xffffffffu, s, o);
        if (lane == 0) sred[rr][(t >> 5) & 1] = s;
        __syncthreads();
        const float inv = 1.f / (sred[rr][0] + sred[rr][1]);
#pragma unroll
        for (int q = 0; q < 8; q++) rowp[q] = e[q] * inv;
    }
    __syncthreads();

    // ---------- Phase C: attended[r][d] = sum_j w[r][j] * h[b,j,d] ----------
    {
        const int d    = t & 127;
        const int part = t >> 7;                      // split j range in 2
        const float* hb = g_h + (size_t)b * kV * kH + d;
        float a0 = 0.f, a1 = 0.f, a2 = 0.f, a3 = 0.f;
        const int j0 = part * 256;
#pragma unroll 4
        for (int j = j0; j < j0 + 256; j++) {
            const float hv = hb[(size_t)j * kH];      // coalesced, L2-hot
            a0 += wS[0 * kV + j] * hv;                // shared broadcast
            a1 += wS[1 * kV + j] * hv;
            a2 += wS[2 * kV + j] * hv;
            a3 += wS[3 * kV + j] * hv;
        }
        attS[(part * kTI + 0) * kH + d] = a0;
        attS[(part * kTI + 1) * kH + d] = a1;
        attS[(part * kTI + 2) * kH + d] = a2;
        attS[(part * kTI + 3) * kH + d] = a3;
    }
    __syncthreads();

    // combine the two j-halves: attS[idx] += attS[512+idx], idx = r*H+d
    attS[t]       = attS[t]       + attS[kTI * kH + t];
    attS[t + 256] = attS[t + 256] + attS[kTI * kH + t + 256];
    __syncthreads();

    // ---------- Phase D: out[b,i0+r,o] = attended[r] . Wo[o,:] + Wob[o] -----
    {
        const float4* att4 = reinterpret_cast<const float4*>(attS);
#pragma unroll
        for (int rep = 0; rep < 2; rep++) {
            const int idx = rep * 256 + t;            // 512 outputs total
            const int r   = idx >> 7;
            const int o   = idx & 127;
            const float4* Wrow = reinterpret_cast<const float4*>(Wo + (size_t)o * kH);
            const float4* arow = att4 + r * (kH / 4);
            float acc = Wob[o];
#pragma unroll
            for (int d = 0; d < kH / 4; d++) {
                float4 wv = Wrow[d];
                float4 av = arow[d];
                acc += wv.x * av.x;
                acc += wv.y * av.y;
                acc += wv.z * av.z;
                acc += wv.w * av.w;
            }
            out[((size_t)(b * kV + i0 + r)) * kH + o] = acc;
        }
    }
}

// ---------------------------------------------------------------------------
// Launch: inputs in metadata order: x, edge_gate, W_w, W_b, a, Wo_w, Wo_b
// ---------------------------------------------------------------------------
extern "C" void kernel_launch(void* const* d_in, const int* in_sizes, int n_in,
                              void* d_out, int out_size)
{
    const float* x   = (const float*)d_in[0];
    const float* eg  = (const float*)d_in[1];
    const float* Ww  = (const float*)d_in[2];
    const float* Wb  = (const float*)d_in[3];
    const float* a   = (const float*)d_in[4];
    const float* Wo  = (const float*)d_in[5];
    const float* Wob = (const float*)d_in[6];
    float* out = (float*)d_out;

    gat_k1<<<kB * kV, 128>>>(x, Ww, Wb, a);
    gat_k2<<<kB * (kV / kTI), 256>>>(eg, Wo, Wob, out);
}

// round 17
// speedup vs baseline: 1.0082x; 1.0082x over previous
#include <cuda_runtime.h>

// Problem constants (fixed by the benchmark shapes)
constexpr int kB  = 4;
constexpr int kV  = 512;
constexpr int kH  = 128;
constexpr int kTI = 4;               // query rows per block in kernel 2

// Scratch (allocation-free rule: __device__ globals)
__device__ float g_h [kB * kV * kH]; // h = x @ W^T + b   (1 MB)
__device__ float g_si[kB * kV];
__device__ float g_sj[kB * kV];

// ---------------------------------------------------------------------------
// Kernel 1: h = x @ W_w^T + W_b ; s_i = h . a_i ; s_j = h . a_j
// One block per (b,v) row, 128 threads (thread = output channel o).
// ---------------------------------------------------------------------------
__global__ void __launch_bounds__(128)
gat_k1(const float* __restrict__ x,
       const float* __restrict__ Ww,
       const float* __restrict__ Wb,
       const float* __restrict__ a)
{
    const int row = blockIdx.x;          // b*V + v
    const int t   = threadIdx.x;         // 0..127

    __shared__ __align__(16) float xs[kH];
    __shared__ float rs[4], rj[4];

    xs[t] = x[(size_t)row * kH + t];
    __syncthreads();

    const float4* xs4 = reinterpret_cast<const float4*>(xs);
    const float4* W4  = reinterpret_cast<const float4*>(Ww + (size_t)t * kH);

    float acc = Wb[t];
#pragma unroll
    for (int d = 0; d < kH / 4; d++) {
        float4 wv = W4[d];
        float4 xv = xs4[d];
        acc += wv.x * xv.x;
        acc += wv.y * xv.y;
        acc += wv.z * xv.z;
        acc += wv.w * xv.w;
    }
    g_h[(size_t)row * kH + t] = acc;

    // a layout: (1, NH=8, 2*HD=32). channel t -> head n = t>>4, k = t&15
    const int n = t >> 4, k = t & 15;
    float si = acc * a[n * 32 + k];
    float sj = acc * a[n * 32 + 16 + k];
#pragma unroll
    for (int o = 16; o; o >>= 1) {
        si += __shfl_xor_sync(0xffffffffu, si, o);
        sj += __shfl_xor_sync(0xffffffffu, sj, o);
    }
    if ((t & 31) == 0) { rs[t >> 5] = si; rj[t >> 5] = sj; }
    __syncthreads();
    if (t == 0) {
        g_si[row] = (rs[0] + rs[1]) + (rs[2] + rs[3]);
        g_sj[row] = (rj[0] + rj[1]) + (rj[2] + rj[3]);
    }
}

// ---------------------------------------------------------------------------
// Kernel 2: per block = (b, 4 consecutive query rows i0..i0+3)
//   A) score[r][j] = leaky_relu(s_i[r]+s_j[j]) * mean_h(edge_gate[b,i,j,:])
//   B) softmax over j (per row)
//   C) attended[r][:] = sum_j w[r][j] * h[b,j,:]   (h L2-resident, 4x reuse)
//   D) out[b,i,:] = attended @ Wo^T + Wo_b         (Wo L1-resident)
// 256 threads, 8 warps.
// ---------------------------------------------------------------------------
__global__ void __launch_bounds__(256)
gat_k2(const float* __restrict__ eg,
       const float* __restrict__ Wo,
       const float* __restrict__ Wob,
       float* __restrict__ out)
{
    const int blk  = blockIdx.x;                 // 0..511
    const int b    = blk >> 7;                   // 128 i-tiles per batch
    const int i0   = (blk & 127) * kTI;
    const int t    = threadIdx.x;
    const int lane = t & 31;
    const int w    = t >> 5;                     // warp id 0..7

    __shared__ float wS[kTI * kV];               // scores -> weights (8 KB)
    __shared__ __align__(16) float attS[2 * kTI * kH]; // partial attended (4 KB)
    __shared__ float sjS[kV];                    // s_j for this batch (2 KB)
    __shared__ float mred[kTI][2], sred[kTI][2];

    // preload s_j row and s_i for our 4 query rows
    sjS[t]       = g_sj[b * kV + t];
    sjS[t + 256] = g_sj[b * kV + t + 256];
    float sib[kTI];
#pragma unroll
    for (int r = 0; r < kTI; r++) sib[r] = g_si[b * kV + i0 + r];
    __syncthreads();

    // ---------- Phase A: stream edge_gate, compute masked leaky scores ------
    {
        const int   r     = w >> 1;                     // warps 2r,2r+1 share row r
        const int   jbase = (w & 1) * 256;
        const float sirow = sib[r];
        const float* egrow = eg + ((size_t)(b * kV + i0 + r)) * kV * kH;

        for (int q = 0; q < 256; q += 4) {
            const int j = jbase + q;
            const float4* p = reinterpret_cast<const float4*>(egrow + (size_t)j * kH) + lane;
            // 4 j-rows in flight per lane: 4 independent LDG.128 (MLP)
            float4 v0 = p[0], v1 = p[32], v2 = p[64], v3 = p[96];
            float p0 = (v0.x + v0.y) + (v0.z + v0.w);
            float p1 = (v1.x + v1.y) + (v1.z + v1.w);
            float p2 = (v2.x + v2.y) + (v2.z + v2.w);
            float p3 = (v3.x + v3.y) + (v3.z + v3.w);
#pragma unroll
            for (int o = 16; o; o >>= 1) {
                p0 += __shfl_xor_sync(0xffffffffu, p0, o);
                p1 += __shfl_xor_sync(0xffffffffu, p1, o);
                p2 += __shfl_xor_sync(0xffffffffu, p2, o);
                p3 += __shfl_xor_sync(0xffffffffu, p3, o);
            }
            if (lane == 0) {
                float s0 = sirow + sjS[j + 0]; s0 = s0 > 0.f ? s0 : 0.2f * s0;
                float s1 = sirow + sjS[j + 1]; s1 = s1 > 0.f ? s1 : 0.2f * s1;
                float s2 = sirow + sjS[j + 2]; s2 = s2 > 0.f ? s2 : 0.2f * s2;
                float s3 = sirow + sjS[j + 3]; s3 = s3 > 0.f ? s3 : 0.2f * s3;
                wS[r * kV + j + 0] = s0 * (p0 * (1.f / 128.f));
                wS[r * kV + j + 1] = s1 * (p1 * (1.f / 128.f));
                wS[r * kV + j + 2] = s2 * (p2 * (1.f / 128.f));
                wS[r * kV + j + 3] = s3 * (p3 * (1.f / 128.f));
            }
        }
    }
    __syncthreads();

    // ---------- Phase B: softmax over j, per row (64 threads / row) ---------
    {
        const int rr = t >> 6;           // row 0..3
        const int c  = t & 63;           // 64 threads per row, 8 elems each
        float* rowp = wS + rr * kV + c * 8;

        float m = rowp[0];
#pragma unroll
        for (int q = 1; q < 8; q++) m = fmaxf(m, rowp[q]);
#pragma unroll
        for (int o = 16; o; o >>= 1) m = fmaxf(m, __shfl_xor_sync(0xffffffffu, m, o));
        if (lane == 0) mred[rr][(t >> 5) & 1] = m;
        __syncthreads();
        const float M = fmaxf(mred[rr][0], mred[rr][1]);

        float e[8];
        float s = 0.f;
#pragma unroll
        for (int q = 0; q < 8; q++) { e[q] = __expf(rowp[q] - M); s += e[q]; }
#pragma unroll
        for (int o = 16; o; o >>= 1) s += __shfl_xor_sync(0xffffffffu, s, o);
        if (lane == 0) sred[rr][(t >> 5) & 1] = s;
        __syncthreads();
        const float inv = 1.f / (sred[rr][0] + sred[rr][1]);
#pragma unroll
        for (int q = 0; q < 8; q++) rowp[q] = e[q] * inv;
    }
    __syncthreads();

    // ---------- Phase C: attended[r][d] = sum_j w[r][j] * h[b,j,d] ----------
    {
        const int d    = t & 127;
        const int part = t >> 7;                      // split j range in 2
        const float* hb = g_h + (size_t)b * kV * kH + d;
        float a0 = 0.f, a1 = 0.f, a2 = 0.f, a3 = 0.f;
        const int j0 = part * 256;
#pragma unroll 4
        for (int j = j0; j < j0 + 256; j++) {
            const float hv = hb[(size_t)j * kH];      // coalesced, L2-hot
            a0 += wS[0 * kV + j] * hv;                // shared broadcast
            a1 += wS[1 * kV + j] * hv;
            a2 += wS[2 * kV + j] * hv;
            a3 += wS[3 * kV + j] * hv;
        }
        attS[(part * kTI + 0) * kH + d] = a0;
        attS[(part * kTI + 1) * kH + d] = a1;
        attS[(part * kTI + 2) * kH + d] = a2;
        attS[(part * kTI + 3) * kH + d] = a3;
    }
    __syncthreads();

    // combine the two j-halves: attS[idx] += attS[512+idx], idx = r*H+d
    attS[t]       = attS[t]       + attS[kTI * kH + t];
    attS[t + 256] = attS[t + 256] + attS[kTI * kH + t + 256];
    __syncthreads();

    // ---------- Phase D: out[b,i0+r,o] = attended[r] . Wo[o,:] + Wob[o] -----
    {
        const float4* att4 = reinterpret_cast<const float4*>(attS);
#pragma unroll
        for (int rep = 0; rep < 2; rep++) {
            const int idx = rep * 256 + t;            // 512 outputs total
            const int r   = idx >> 7;
            const int o   = idx & 127;
            const float4* Wrow = reinterpret_cast<const float4*>(Wo + (size_t)o * kH);
            const float4* arow = att4 + r * (kH / 4);
            float acc = Wob[o];
#pragma unroll
            for (int d = 0; d < kH / 4; d++) {
                float4 wv = Wrow[d];
                float4 av = arow[d];
                acc += wv.x * av.x;
                acc += wv.y * av.y;
                acc += wv.z * av.z;
                acc += wv.w * av.w;
            }
            out[((size_t)(b * kV + i0 + r)) * kH + o] = acc;
        }
    }
}

// ---------------------------------------------------------------------------
// Launch: inputs in metadata order: x, edge_gate, W_w, W_b, a, Wo_w, Wo_b
// ---------------------------------------------------------------------------
extern "C" void kernel_launch(void* const* d_in, const int* in_sizes, int n_in,
                              void* d_out, int out_size)
{
    const float* x   = (const float*)d_in[0];
    const float* eg  = (const float*)d_in[1];
    const float* Ww  = (const float*)d_in[2];
    const float* Wb  = (const float*)d_in[3];
    const float* a   = (const float*)d_in[4];
    const float* Wo  = (const float*)d_in[5];
    const float* Wob = (const float*)d_in[6];
    float* out = (float*)d_out;

    gat_k1<<<kB * kV, 128>>>(x, Ww, Wb, a);
    gat_k2<<<kB * (kV / kTI), 256>>>(eg, Wo, Wob, out);
}